// round 15
// baseline (speedup 1.0000x reference)
#include <cuda_runtime.h>
#include <cuda_bf16.h>
#include <cstdint>

// ---------------- Problem constants ----------------
#define NB    8
#define SD    512
#define CIN   512
#define COUT  512
#define CPG   64
#define NG    8
#define HH    64
#define WW    64
#define HWSZ  4096
#define KDK   4608
#define ODK   32768
#define NCOL  72
#define NSTEP 288          // KDK / 16
#define KSPLIT 4
#define QSTEP (NSTEP / KSPLIT)   // 72
#define NTIL  9            // 72 / 8
#define BSTG  (NTIL * 32)  // 288 uint4 per B stage
#define DWSZ  (NB * CPG * 9 * COUT)

typedef unsigned long long ull;

// ---------------- Device scratch ----------------
__device__ float g_pooled[NB * SD];
__device__ float g_pwkn[NB * ODK];
__device__ float g_pwbias[NB * COUT];
__device__ __align__(16) uint4 g_Bfrag[NSTEP * NTIL * 32];   // K-permuted bf16 hi/lo B fragments
__device__ float g_dwP[KSPLIT][DWSZ];                        // K-quarter partials
__device__ float g_dwT[DWSZ];                                // merged depthwise weights [n][ci][k][co]

// ---------------- f32x2 helpers (k_conv) ----------------
__device__ __forceinline__ ull pk2(float lo, float hi) {
    ull r;
    asm("mov.b64 %0, {%1, %2};" : "=l"(r) : "f"(lo), "f"(hi));
    return r;
}
__device__ __forceinline__ void upk2(ull v, float& lo, float& hi) {
    asm("mov.b64 {%0, %1}, %2;" : "=f"(lo), "=f"(hi) : "l"(v));
}
__device__ __forceinline__ void fma2(ull& d, ull a, ull b) {
    asm("fma.rn.f32x2 %0, %1, %2, %0;" : "+l"(d) : "l"(a), "l"(b));
}

// ---------------- mma.sync / cp.async helpers ----------------
__device__ __forceinline__ void mma16816(float* c, const uint32_t* a, uint32_t b0, uint32_t b1) {
    asm volatile(
        "mma.sync.aligned.m16n8k16.row.col.f32.bf16.bf16.f32 "
        "{%0,%1,%2,%3}, {%4,%5,%6,%7}, {%8,%9}, {%0,%1,%2,%3};"
        : "+f"(c[0]), "+f"(c[1]), "+f"(c[2]), "+f"(c[3])
        : "r"(a[0]), "r"(a[1]), "r"(a[2]), "r"(a[3]), "r"(b0), "r"(b1));
}
__device__ __forceinline__ uint32_t bf2u(__nv_bfloat162 h) {
    return *(const uint32_t*)&h;
}
__device__ __forceinline__ void cp16(uint32_t saddr, const void* gaddr) {
    asm volatile("cp.async.cg.shared.global [%0], [%1], 16;" :: "r"(saddr), "l"(gaddr));
}
#define CP_COMMIT() asm volatile("cp.async.commit_group;" ::: "memory")
#define CP_WAIT1()  asm volatile("cp.async.wait_group 1;" ::: "memory")

// ---------------- K0: 3x3 avg pool ----------------
__global__ void k_pool(const float* __restrict__ style) {
    int i = blockIdx.x * blockDim.x + threadIdx.x;
    if (i >= NB * SD) return;
    const float* p = style + (size_t)i * 25;
    float s = 0.f;
#pragma unroll
    for (int y = 0; y < 3; y++)
#pragma unroll
        for (int x = 0; x < 3; x++)
            s += p[y * 5 + x];
    g_pooled[i] = s * (1.0f / 9.0f);
}

// ---------------- K0b: build K-PERMUTED B fragments ----------------
__device__ __forceinline__ float bval(const float* style, int n, int k) {
    int batch = n / 9, q = n % 9;
    int y = q / 3, x = q % 3;
    int sc = k / 9, rr = k % 9;
    int dy = rr / 3, dx = rr % 3;
    return style[((size_t)(batch * SD + sc) * 5 + (y + dy)) * 5 + (x + dx)];
}

__global__ void k_buildB(const float* __restrict__ style) {
    int i = blockIdx.x * blockDim.x + threadIdx.x;
    if (i >= NSTEP * NTIL * 32) return;
    int lane = i & 31;
    int t = i >> 5;
    int nt = t % NTIL;
    int s = t / NTIL;
    int n = nt * 8 + (lane >> 2);
    int kb = s * 16 + (lane & 3) * 4;          // contiguous 4 mem-k per thread (permuted)
    float v[4];
#pragma unroll
    for (int q = 0; q < 4; q++) v[q] = bval(style, n, kb + q);
    __nv_bfloat16 h[4];
    float l[4];
#pragma unroll
    for (int q = 0; q < 4; q++) {
        h[q] = __float2bfloat16(v[q]);
        l[q] = v[q] - __bfloat162float(h[q]);
    }
    uint4 out;
    out.x = bf2u(__nv_bfloat162(h[0], h[1]));
    out.y = bf2u(__nv_bfloat162(h[2], h[3]));
    out.z = bf2u(__floats2bfloat162_rn(l[0], l[1]));
    out.w = bf2u(__floats2bfloat162_rn(l[2], l[3]));
    g_Bfrag[t * 32 + lane] = out;
}

// ---------------- K1: pooled GEMVs ----------------
__global__ void __launch_bounds__(256) k_pw(const float* __restrict__ Wpwk, const float* __restrict__ bpwk,
                                            const float* __restrict__ Wpwb, const float* __restrict__ bpwb) {
    __shared__ float ps[NB * SD];
    int tid = threadIdx.x;
    for (int i = tid; i < NB * SD; i += 256) ps[i] = g_pooled[i];
    __syncthreads();

    int r = blockIdx.x * 256 + tid;
    if (r >= ODK + COUT) return;
    bool isk = (r < ODK);
    int rr = isk ? r : (r - ODK);
    const float* w = isk ? (Wpwk + (size_t)r * SD) : (Wpwb + (size_t)rr * SD);
    float bias = isk ? bpwk[r] : bpwb[rr];

    float acc[NB];
#pragma unroll
    for (int n = 0; n < NB; n++) acc[n] = 0.f;

    for (int s = 0; s < SD; s += 4) {
        float4 wv = *(const float4*)(w + s);
#pragma unroll
        for (int n = 0; n < NB; n++) {
            const float* pp = &ps[n * SD + s];
            acc[n] += wv.x * pp[0] + wv.y * pp[1] + wv.z * pp[2] + wv.w * pp[3];
        }
    }
    if (isk) {
#pragma unroll
        for (int n = 0; n < NB; n++) g_pwkn[(size_t)n * ODK + r] = acc[n] + bias;
    } else {
#pragma unroll
        for (int n = 0; n < NB; n++) g_pwbias[n * COUT + rr] = acc[n] + bias;
    }
}

// ---------------- K2: dk GEMM, M=32/warp, K-permuted LDG.128 A, K-split 4 ----------------
__global__ void __launch_bounds__(128) k_dk(const float* __restrict__ Wdk) {
    __shared__ __align__(16) uint4 Bs[3][BSTG];

    int tid = threadIdx.x;
    int wid = tid >> 5, lane = tid & 31;
    int bx = blockIdx.x;
    int kq = bx & 3;
    int mb = bx >> 2;
    int m0 = mb * 128 + wid * 32;
    int rA = m0 + (lane >> 2);
    int q4 = (lane & 3) * 4;
    int kc2 = (lane & 3) * 2;
    int sbase = kq * QSTEP;

    const float* aBase = Wdk + (size_t)rA * KDK + q4 + (size_t)sbase * 16;
    const size_t r8 = (size_t)8 * KDK;
    const uint4* bfrag0 = g_Bfrag + (size_t)sbase * BSTG;

    uint32_t bs_addr[3];
#pragma unroll
    for (int b = 0; b < 3; b++) bs_addr[b] = (uint32_t)__cvta_generic_to_shared(&Bs[b][0]);

    float acc[2][NTIL][4];
#pragma unroll
    for (int j = 0; j < 2; j++)
#pragma unroll
        for (int nt = 0; nt < NTIL; nt++)
#pragma unroll
            for (int q = 0; q < 4; q++) acc[j][nt][q] = 0.f;

    float4 pa[2][4];
#pragma unroll
    for (int d = 0; d < 2; d++) {
        const float* ap = aBase + (size_t)d * 16;
        pa[d][0] = *(const float4*)(ap);
        pa[d][1] = *(const float4*)(ap + r8);
        pa[d][2] = *(const float4*)(ap + 2 * r8);
        pa[d][3] = *(const float4*)(ap + 3 * r8);
    }
#pragma unroll
    for (int st = 0; st < 2; st++) {
        const uint4* src = bfrag0 + (size_t)st * BSTG;
        cp16(bs_addr[st] + tid * 16, src + tid);
        cp16(bs_addr[st] + (tid + 128) * 16, src + tid + 128);
        if (tid < 32) cp16(bs_addr[st] + (tid + 256) * 16, src + tid + 256);
        CP_COMMIT();
    }
    CP_WAIT1();
    __syncthreads();

    for (int s = 0; s < QSTEP; s++) {
        int cb = s & 1;
        uint32_t ahi[2][4], alo[2][4];
#pragma unroll
        for (int j = 0; j < 2; j++) {
            float4 fr = pa[cb][2 * j];
            float4 f8 = pa[cb][2 * j + 1];
            __nv_bfloat162 h0 = __floats2bfloat162_rn(fr.x, fr.y);
            __nv_bfloat162 h1 = __floats2bfloat162_rn(f8.x, f8.y);
            __nv_bfloat162 h2 = __floats2bfloat162_rn(fr.z, fr.w);
            __nv_bfloat162 h3 = __floats2bfloat162_rn(f8.z, f8.w);
            ahi[j][0] = bf2u(h0); ahi[j][1] = bf2u(h1); ahi[j][2] = bf2u(h2); ahi[j][3] = bf2u(h3);
            alo[j][0] = bf2u(__floats2bfloat162_rn(fr.x - __low2float(h0), fr.y - __high2float(h0)));
            alo[j][1] = bf2u(__floats2bfloat162_rn(f8.x - __low2float(h1), f8.y - __high2float(h1)));
            alo[j][2] = bf2u(__floats2bfloat162_rn(fr.z - __low2float(h2), fr.w - __high2float(h2)));
            alo[j][3] = bf2u(__floats2bfloat162_rn(f8.z - __low2float(h3), f8.w - __high2float(h3)));
        }
        if (s + 2 < QSTEP) {
            const float* ap = aBase + (size_t)(s + 2) * 16;
            pa[cb][0] = *(const float4*)(ap);
            pa[cb][1] = *(const float4*)(ap + r8);
            pa[cb][2] = *(const float4*)(ap + 2 * r8);
            pa[cb][3] = *(const float4*)(ap + 3 * r8);
        }
        if (s + 2 < QSTEP) {
            int nb = (s + 2) % 3;
            const uint4* src = bfrag0 + (size_t)(s + 2) * BSTG;
            cp16(bs_addr[nb] + tid * 16, src + tid);
            cp16(bs_addr[nb] + (tid + 128) * 16, src + tid + 128);
            if (tid < 32) cp16(bs_addr[nb] + (tid + 256) * 16, src + tid + 256);
        }
        CP_COMMIT();
        const uint4* bsrow = &Bs[s % 3][lane];
#pragma unroll
        for (int nt = 0; nt < NTIL; nt++) {
            uint4 b = bsrow[nt * 32];
            mma16816(acc[0][nt], ahi[0], b.x, b.y);
            mma16816(acc[0][nt], ahi[0], b.z, b.w);
            mma16816(acc[0][nt], alo[0], b.x, b.y);
            mma16816(acc[1][nt], ahi[1], b.x, b.y);
            mma16816(acc[1][nt], ahi[1], b.z, b.w);
            mma16816(acc[1][nt], alo[1], b.x, b.y);
        }
        CP_WAIT1();
        __syncthreads();
    }

    float* dst = g_dwP[kq];
#pragma unroll
    for (int j = 0; j < 2; j++) {
        int o0 = rA + 16 * j, o1 = o0 + 8;
        int co0 = o0 >> 6, ci0 = o0 & 63;
        int co1 = o1 >> 6, ci1 = o1 & 63;
#pragma unroll
        for (int nt = 0; nt < NTIL; nt++) {
            int colb = nt * 8 + kc2;
#pragma unroll
            for (int d = 0; d < 2; d++) {
                int col = colb + d;
                int n = col / 9, jj = col % 9;
                dst[((size_t)((n * CPG + ci0) * 9 + jj)) * COUT + co0] = acc[j][nt][d];
                dst[((size_t)((n * CPG + ci1) * 9 + jj)) * COUT + co1] = acc[j][nt][2 + d];
            }
        }
    }
}

// ---------------- K2b: merge K-quarter partials + bias ----------------
__global__ void __launch_bounds__(256) k_red(const float* __restrict__ bdk) {
    int i = blockIdx.x * 256 + threadIdx.x;
    if (i >= DWSZ) return;
    int co = i & 511;
    int ci = (i / (9 * 512)) & 63;
    float b = bdk[co * 64 + ci];
    g_dwT[i] = g_dwP[0][i] + g_dwP[1][i] + g_dwP[2][i] + g_dwP[3][i] + b;
}

// ---------------- K3: fused depthwise+pointwise, 512 thr, 8 rows/block ----------------
#define RPB      8
#define IN_OFF   (CPG * RPB * WW)               // 32768 floats (depth tile)
#define BUFSZ    1360                           // (680 main + 680 shifted) per buffer
#define PW_OFF   (IN_OFF + 2 * BUFSZ)           // 35488
#define SMEM_CONV ((PW_OFF + CPG * CPG) * 4)    // 158336 B

__device__ __forceinline__ int refl(int i) {
    return i < 0 ? -i : (i > 63 ? 126 - i : i);
}

__global__ void __launch_bounds__(512) k_conv(const float* __restrict__ pred, float* __restrict__ out) {
    extern __shared__ __align__(16) float sm[];
    float* depth_s = sm;                 // [cm][hl(8)][w]
    float* in_base = sm + IN_OFF;        // 2 buffers of [680 main | 680 shifted], rows 10x68
    float* pw_s    = sm + PW_OFF;

    int tid = threadIdx.x;
    int co = tid & 63;
    int hl = tid >> 6;                   // 0..7
    int rb = blockIdx.x, g = blockIdx.y, n = blockIdx.z;
    int h0 = rb * RPB;

    const float* base = pred + (size_t)(n * CIN + g * CPG) * HWSZ;

    for (int i = tid; i < CPG * CPG; i += 512) {
        int cm = i >> 6, c = i & 63;
        pw_s[i] = g_pwkn[(size_t)n * ODK + (g * CPG + c) * CPG + cm];
    }

    // loader geometry: 660 positions (10 rows x 66 cols); i0 = tid (<512 always valid), i1 sparse
    int i0 = tid, i1 = tid + 512;
    int r0 = i0 / 66, c0p = i0 % 66;
    int r1 = i1 / 66, c1p = i1 % 66;
    bool v1 = (i1 < 660);
    int goff0 = refl(h0 + r0 - 1) * WW + refl(c0p - 1);
    int goff1 = v1 ? (refl(h0 + r1 - 1) * WW + refl(c1p - 1)) : 0;
    int s0 = r0 * 68 + c0p;
    int s1 = r1 * 68 + c1p;

    float q0 = base[goff0];
    float q1 = v1 ? base[goff1] : 0.f;
    const float* wp = g_dwT + ((size_t)(n * CPG) * 9) * COUT + (g * CPG + co);
    float dcur[9], dnxt[9];
#pragma unroll
    for (int k = 0; k < 9; k++) dcur[k] = wp[k * COUT];

    ull acc2[32];
#pragma unroll
    for (int i = 0; i < 32; i++) acc2[i] = 0ULL;

    for (int ci = 0; ci < CPG; ci++) {
        float* ia = in_base + (ci & 1) * BUFSZ;
        float* ib = ia + 680;
        ia[s0] = q0;
        if (c0p) ib[s0 - 1] = q0;
        if (v1) {
            ia[s1] = q1;
            if (c1p) ib[s1 - 1] = q1;
        }
        __syncthreads();

        if (ci + 1 < CPG) {
            const float* pl = base + (size_t)(ci + 1) * HWSZ;
            q0 = pl[goff0];
            q1 = v1 ? pl[goff1] : 0.f;
            const float* wn = wp + (size_t)(ci + 1) * 9 * COUT;
#pragma unroll
            for (int k = 0; k < 9; k++) dnxt[k] = wn[k * COUT];
        }

#pragma unroll
        for (int kh = 0; kh < 3; kh++) {
            const float* row  = &ia[(hl + kh) * 68];
            const float* rowB = row + 680;
            ull w0 = pk2(dcur[kh * 3 + 0], dcur[kh * 3 + 0]);
            ull w1 = pk2(dcur[kh * 3 + 1], dcur[kh * 3 + 1]);
            ull w2 = pk2(dcur[kh * 3 + 2], dcur[kh * 3 + 2]);
#pragma unroll
            for (int c0 = 0; c0 < 64; c0 += 16) {
                const ull* ra = (const ull*)(row + c0);
                ulonglong2 a01 = *(const ulonglong2*)(ra);
                ulonglong2 a23 = *(const ulonglong2*)(ra + 2);
                ulonglong2 a45 = *(const ulonglong2*)(ra + 4);
                ulonglong2 a67 = *(const ulonglong2*)(ra + 6);
                ull a8 = ra[8];
                const ull* rbp = (const ull*)(rowB + c0);
                ulonglong2 b01 = *(const ulonglong2*)(rbp);
                ulonglong2 b23 = *(const ulonglong2*)(rbp + 2);
                ulonglong2 b45 = *(const ulonglong2*)(rbp + 4);
                ulonglong2 b67 = *(const ulonglong2*)(rbp + 6);
                int p = c0 >> 1;
                fma2(acc2[p + 0], w0, a01.x); fma2(acc2[p + 0], w1, b01.x); fma2(acc2[p + 0], w2, a01.y);
                fma2(acc2[p + 1], w0, a01.y); fma2(acc2[p + 1], w1, b01.y); fma2(acc2[p + 1], w2, a23.x);
                fma2(acc2[p + 2], w0, a23.x); fma2(acc2[p + 2], w1, b23.x); fma2(acc2[p + 2], w2, a23.y);
                fma2(acc2[p + 3], w0, a23.y); fma2(acc2[p + 3], w1, b23.y); fma2(acc2[p + 3], w2, a45.x);
                fma2(acc2[p + 4], w0, a45.x); fma2(acc2[p + 4], w1, b45.x); fma2(acc2[p + 4], w2, a45.y);
                fma2(acc2[p + 5], w0, a45.y); fma2(acc2[p + 5], w1, b45.y); fma2(acc2[p + 5], w2, a67.x);
                fma2(acc2[p + 6], w0, a67.x); fma2(acc2[p + 6], w1, b67.x); fma2(acc2[p + 6], w2, a67.y);
                fma2(acc2[p + 7], w0, a67.y); fma2(acc2[p + 7], w1, b67.y); fma2(acc2[p + 7], w2, a8);
            }
        }
#pragma unroll
        for (int k = 0; k < 9; k++) dcur[k] = dnxt[k];
    }

    __syncthreads();
    {
        ull* dst = (ull*)(depth_s + (co * RPB + hl) * 64);
#pragma unroll
        for (int i = 0; i < 32; i++) dst[i] = acc2[i];
    }
    __syncthreads();

#pragma unroll
    for (int i = 0; i < 32; i++) acc2[i] = 0ULL;
    for (int cm = 0; cm < CPG; cm++) {
        float v = pw_s[cm * 64 + co];
        ull vp = pk2(v, v);
        const ulonglong2* ds = (const ulonglong2*)(depth_s + (cm * RPB + hl) * 64);
#pragma unroll
        for (int i = 0; i < 16; i++) {
            ulonglong2 t = ds[i];
            fma2(acc2[2 * i],     vp, t.x);
            fma2(acc2[2 * i + 1], vp, t.y);
        }
    }

    float bias = g_pwbias[n * COUT + g * CPG + co];
    float* op = out + (((size_t)(n * COUT + g * CPG + co)) * HH + (h0 + hl)) * WW;
#pragma unroll
    for (int i = 0; i < 16; i++) {
        float x0, x1, x2, x3;
        upk2(acc2[2 * i], x0, x1);
        upk2(acc2[2 * i + 1], x2, x3);
        *(float4*)(op + 4 * i) = make_float4(x0 + bias, x1 + bias, x2 + bias, x3 + bias);
    }
}

// ---------------- Launch ----------------
extern "C" void kernel_launch(void* const* d_in, const int* in_sizes, int n_in,
                              void* d_out, int out_size) {
    const float* style = (const float*)d_in[0];
    const float* pred  = (const float*)d_in[1];
    const float* Wdk   = (const float*)d_in[2];
    const float* bdk   = (const float*)d_in[3];
    const float* Wpwk  = (const float*)d_in[4];
    const float* bpwk  = (const float*)d_in[5];
    const float* Wpwb  = (const float*)d_in[6];
    const float* bpwb  = (const float*)d_in[7];
    float* out = (float*)d_out;

    cudaFuncSetAttribute(k_conv, cudaFuncAttributeMaxDynamicSharedMemorySize, SMEM_CONV);

    k_pool<<<(NB * SD + 255) / 256, 256>>>(style);
    k_buildB<<<(NSTEP * NTIL * 32 + 255) / 256, 256>>>(style);
    k_pw<<<(ODK + COUT + 255) / 256, 256>>>(Wpwk, bpwk, Wpwb, bpwb);
    k_dk<<<(ODK / 128) * KSPLIT, 128>>>(Wdk);
    k_red<<<(DWSZ + 255) / 256, 256>>>(bdk);
    k_conv<<<dim3(HH / RPB, NG, NB), 512, SMEM_CONV>>>(pred, out);
}

// round 16
// speedup vs baseline: 1.2352x; 1.2352x over previous
#include <cuda_runtime.h>
#include <cuda_bf16.h>
#include <cstdint>

// ---------------- Problem constants ----------------
#define NB    8
#define SD    512
#define CIN   512
#define COUT  512
#define CPG   64
#define NG    8
#define HH    64
#define WW    64
#define HWSZ  4096
#define KDK   4608
#define ODK   32768
#define NCOL  72
#define NSTEP 288          // KDK / 16
#define KSPLIT 4
#define QSTEP (NSTEP / KSPLIT)   // 72
#define NTIL  9            // 72 / 8
#define BSTG  (NTIL * 32)  // 288 uint4 per B stage
#define WREC  12           // padded taps per (n,ci,co) record (48B, 16B-aligned)
#define DWSZ12 (NB * CPG * COUT * WREC)

typedef unsigned long long ull;

// ---------------- Device scratch ----------------
__device__ float g_pooled[NB * SD];
__device__ float g_pwkn[NB * ODK];
__device__ float g_pwbias[NB * COUT];
__device__ __align__(16) uint4 g_Bfrag[NSTEP * NTIL * 32];   // K-permuted bf16 hi/lo B fragments
__device__ __align__(16) float g_dwP[KSPLIT][DWSZ12];        // K-quarter partials, [n][ci][co][12]
__device__ __align__(16) float g_dwT[DWSZ12];                // merged weights [n][ci][co][12]

// ---------------- f32x2 helpers (k_conv) ----------------
__device__ __forceinline__ ull pk2(float lo, float hi) {
    ull r;
    asm("mov.b64 %0, {%1, %2};" : "=l"(r) : "f"(lo), "f"(hi));
    return r;
}
__device__ __forceinline__ void upk2(ull v, float& lo, float& hi) {
    asm("mov.b64 {%0, %1}, %2;" : "=f"(lo), "=f"(hi) : "l"(v));
}
__device__ __forceinline__ void fma2(ull& d, ull a, ull b) {
    asm("fma.rn.f32x2 %0, %1, %2, %0;" : "+l"(d) : "l"(a), "l"(b));
}

// ---------------- mma.sync / cp.async helpers ----------------
__device__ __forceinline__ void mma16816(float* c, const uint32_t* a, uint32_t b0, uint32_t b1) {
    asm volatile(
        "mma.sync.aligned.m16n8k16.row.col.f32.bf16.bf16.f32 "
        "{%0,%1,%2,%3}, {%4,%5,%6,%7}, {%8,%9}, {%0,%1,%2,%3};"
        : "+f"(c[0]), "+f"(c[1]), "+f"(c[2]), "+f"(c[3])
        : "r"(a[0]), "r"(a[1]), "r"(a[2]), "r"(a[3]), "r"(b0), "r"(b1));
}
__device__ __forceinline__ uint32_t bf2u(__nv_bfloat162 h) {
    return *(const uint32_t*)&h;
}
__device__ __forceinline__ void cp16(uint32_t saddr, const void* gaddr) {
    asm volatile("cp.async.cg.shared.global [%0], [%1], 16;" :: "r"(saddr), "l"(gaddr));
}
#define CP_COMMIT() asm volatile("cp.async.commit_group;" ::: "memory")
#define CP_WAIT1()  asm volatile("cp.async.wait_group 1;" ::: "memory")

// ---------------- K0: 3x3 avg pool ----------------
__global__ void k_pool(const float* __restrict__ style) {
    int i = blockIdx.x * blockDim.x + threadIdx.x;
    if (i >= NB * SD) return;
    const float* p = style + (size_t)i * 25;
    float s = 0.f;
#pragma unroll
    for (int y = 0; y < 3; y++)
#pragma unroll
        for (int x = 0; x < 3; x++)
            s += p[y * 5 + x];
    g_pooled[i] = s * (1.0f / 9.0f);
}

// ---------------- K0b: build K-PERMUTED B fragments ----------------
__device__ __forceinline__ float bval(const float* style, int n, int k) {
    int batch = n / 9, q = n % 9;
    int y = q / 3, x = q % 3;
    int sc = k / 9, rr = k % 9;
    int dy = rr / 3, dx = rr % 3;
    return style[((size_t)(batch * SD + sc) * 5 + (y + dy)) * 5 + (x + dx)];
}

__global__ void k_buildB(const float* __restrict__ style) {
    int i = blockIdx.x * blockDim.x + threadIdx.x;
    if (i >= NSTEP * NTIL * 32) return;
    int lane = i & 31;
    int t = i >> 5;
    int nt = t % NTIL;
    int s = t / NTIL;
    int n = nt * 8 + (lane >> 2);
    int kb = s * 16 + (lane & 3) * 4;          // contiguous 4 mem-k per thread (permuted)
    float v[4];
#pragma unroll
    for (int q = 0; q < 4; q++) v[q] = bval(style, n, kb + q);
    __nv_bfloat16 h[4];
    float l[4];
#pragma unroll
    for (int q = 0; q < 4; q++) {
        h[q] = __float2bfloat16(v[q]);
        l[q] = v[q] - __bfloat162float(h[q]);
    }
    uint4 out;
    out.x = bf2u(__nv_bfloat162(h[0], h[1]));
    out.y = bf2u(__nv_bfloat162(h[2], h[3]));
    out.z = bf2u(__floats2bfloat162_rn(l[0], l[1]));
    out.w = bf2u(__floats2bfloat162_rn(l[2], l[3]));
    g_Bfrag[t * 32 + lane] = out;
}

// ---------------- K1: pooled GEMVs ----------------
__global__ void __launch_bounds__(256) k_pw(const float* __restrict__ Wpwk, const float* __restrict__ bpwk,
                                            const float* __restrict__ Wpwb, const float* __restrict__ bpwb) {
    __shared__ float ps[NB * SD];
    int tid = threadIdx.x;
    for (int i = tid; i < NB * SD; i += 256) ps[i] = g_pooled[i];
    __syncthreads();

    int r = blockIdx.x * 256 + tid;
    if (r >= ODK + COUT) return;
    bool isk = (r < ODK);
    int rr = isk ? r : (r - ODK);
    const float* w = isk ? (Wpwk + (size_t)r * SD) : (Wpwb + (size_t)rr * SD);
    float bias = isk ? bpwk[r] : bpwb[rr];

    float acc[NB];
#pragma unroll
    for (int n = 0; n < NB; n++) acc[n] = 0.f;

    for (int s = 0; s < SD; s += 4) {
        float4 wv = *(const float4*)(w + s);
#pragma unroll
        for (int n = 0; n < NB; n++) {
            const float* pp = &ps[n * SD + s];
            acc[n] += wv.x * pp[0] + wv.y * pp[1] + wv.z * pp[2] + wv.w * pp[3];
        }
    }
    if (isk) {
#pragma unroll
        for (int n = 0; n < NB; n++) g_pwkn[(size_t)n * ODK + r] = acc[n] + bias;
    } else {
#pragma unroll
        for (int n = 0; n < NB; n++) g_pwbias[n * COUT + rr] = acc[n] + bias;
    }
}

// ---------------- K2: dk GEMM, M=32/warp, K-permuted LDG.128 A, K-split 4 ----------------
__global__ void __launch_bounds__(128) k_dk(const float* __restrict__ Wdk) {
    __shared__ __align__(16) uint4 Bs[3][BSTG];

    int tid = threadIdx.x;
    int wid = tid >> 5, lane = tid & 31;
    int bx = blockIdx.x;
    int kq = bx & 3;
    int mb = bx >> 2;
    int m0 = mb * 128 + wid * 32;
    int rA = m0 + (lane >> 2);
    int q4 = (lane & 3) * 4;
    int kc2 = (lane & 3) * 2;
    int sbase = kq * QSTEP;

    const float* aBase = Wdk + (size_t)rA * KDK + q4 + (size_t)sbase * 16;
    const size_t r8 = (size_t)8 * KDK;
    const uint4* bfrag0 = g_Bfrag + (size_t)sbase * BSTG;

    uint32_t bs_addr[3];
#pragma unroll
    for (int b = 0; b < 3; b++) bs_addr[b] = (uint32_t)__cvta_generic_to_shared(&Bs[b][0]);

    float acc[2][NTIL][4];
#pragma unroll
    for (int j = 0; j < 2; j++)
#pragma unroll
        for (int nt = 0; nt < NTIL; nt++)
#pragma unroll
            for (int q = 0; q < 4; q++) acc[j][nt][q] = 0.f;

    float4 pa[2][4];
#pragma unroll
    for (int d = 0; d < 2; d++) {
        const float* ap = aBase + (size_t)d * 16;
        pa[d][0] = *(const float4*)(ap);
        pa[d][1] = *(const float4*)(ap + r8);
        pa[d][2] = *(const float4*)(ap + 2 * r8);
        pa[d][3] = *(const float4*)(ap + 3 * r8);
    }
#pragma unroll
    for (int st = 0; st < 2; st++) {
        const uint4* src = bfrag0 + (size_t)st * BSTG;
        cp16(bs_addr[st] + tid * 16, src + tid);
        cp16(bs_addr[st] + (tid + 128) * 16, src + tid + 128);
        if (tid < 32) cp16(bs_addr[st] + (tid + 256) * 16, src + tid + 256);
        CP_COMMIT();
    }
    CP_WAIT1();
    __syncthreads();

    for (int s = 0; s < QSTEP; s++) {
        int cb = s & 1;
        uint32_t ahi[2][4], alo[2][4];
#pragma unroll
        for (int j = 0; j < 2; j++) {
            float4 fr = pa[cb][2 * j];
            float4 f8 = pa[cb][2 * j + 1];
            __nv_bfloat162 h0 = __floats2bfloat162_rn(fr.x, fr.y);
            __nv_bfloat162 h1 = __floats2bfloat162_rn(f8.x, f8.y);
            __nv_bfloat162 h2 = __floats2bfloat162_rn(fr.z, fr.w);
            __nv_bfloat162 h3 = __floats2bfloat162_rn(f8.z, f8.w);
            ahi[j][0] = bf2u(h0); ahi[j][1] = bf2u(h1); ahi[j][2] = bf2u(h2); ahi[j][3] = bf2u(h3);
            alo[j][0] = bf2u(__floats2bfloat162_rn(fr.x - __low2float(h0), fr.y - __high2float(h0)));
            alo[j][1] = bf2u(__floats2bfloat162_rn(f8.x - __low2float(h1), f8.y - __high2float(h1)));
            alo[j][2] = bf2u(__floats2bfloat162_rn(fr.z - __low2float(h2), fr.w - __high2float(h2)));
            alo[j][3] = bf2u(__floats2bfloat162_rn(f8.z - __low2float(h3), f8.w - __high2float(h3)));
        }
        if (s + 2 < QSTEP) {
            const float* ap = aBase + (size_t)(s + 2) * 16;
            pa[cb][0] = *(const float4*)(ap);
            pa[cb][1] = *(const float4*)(ap + r8);
            pa[cb][2] = *(const float4*)(ap + 2 * r8);
            pa[cb][3] = *(const float4*)(ap + 3 * r8);
        }
        if (s + 2 < QSTEP) {
            int nb = (s + 2) % 3;
            const uint4* src = bfrag0 + (size_t)(s + 2) * BSTG;
            cp16(bs_addr[nb] + tid * 16, src + tid);
            cp16(bs_addr[nb] + (tid + 128) * 16, src + tid + 128);
            if (tid < 32) cp16(bs_addr[nb] + (tid + 256) * 16, src + tid + 256);
        }
        CP_COMMIT();
        const uint4* bsrow = &Bs[s % 3][lane];
#pragma unroll
        for (int nt = 0; nt < NTIL; nt++) {
            uint4 b = bsrow[nt * 32];
            mma16816(acc[0][nt], ahi[0], b.x, b.y);
            mma16816(acc[0][nt], ahi[0], b.z, b.w);
            mma16816(acc[0][nt], alo[0], b.x, b.y);
            mma16816(acc[1][nt], ahi[1], b.x, b.y);
            mma16816(acc[1][nt], ahi[1], b.z, b.w);
            mma16816(acc[1][nt], alo[1], b.x, b.y);
        }
        CP_WAIT1();
        __syncthreads();
    }

    // epilogue: partials into [n][ci][co][12] layout
    float* dst = g_dwP[kq];
#pragma unroll
    for (int j = 0; j < 2; j++) {
        int o0 = rA + 16 * j, o1 = o0 + 8;
        int co0 = o0 >> 6, ci0 = o0 & 63;
        int co1 = o1 >> 6, ci1 = o1 & 63;
#pragma unroll
        for (int nt = 0; nt < NTIL; nt++) {
            int colb = nt * 8 + kc2;
#pragma unroll
            for (int d = 0; d < 2; d++) {
                int col = colb + d;
                int n = col / 9, jj = col % 9;
                dst[((size_t)((n * CPG + ci0) * COUT) + co0) * WREC + jj] = acc[j][nt][d];
                dst[((size_t)((n * CPG + ci1) * COUT) + co1) * WREC + jj] = acc[j][nt][2 + d];
            }
        }
    }
}

// ---------------- K2b: merge K-quarter partials + bias (new layout) ----------------
__global__ void __launch_bounds__(256) k_red(const float* __restrict__ bdk) {
    int i = blockIdx.x * 256 + threadIdx.x;
    if (i >= DWSZ12) return;
    int k = i % WREC;
    if (k >= 9) return;                    // pad lanes never read
    int rec = i / WREC;
    int co = rec & 511;
    int ci = (rec >> 9) & 63;
    float b = bdk[co * 64 + ci];
    g_dwT[i] = g_dwP[0][i] + g_dwP[1][i] + g_dwP[2][i] + g_dwP[3][i] + b;
}

// ---------------- K3: fused depthwise+pointwise (R14 structure, reduced regs) ----------------
#define IN_OFF   (CPG * 4 * WW)
#define BUFSZ    816
#define PW_OFF   (IN_OFF + 2 * BUFSZ)
#define SMEM_CONV ((PW_OFF + CPG * CPG) * 4)

__device__ __forceinline__ int refl(int i) {
    return i < 0 ? -i : (i > 63 ? 126 - i : i);
}

__global__ void __launch_bounds__(256, 2) k_conv(const float* __restrict__ pred, float* __restrict__ out) {
    extern __shared__ __align__(16) float sm[];
    float* depth_s = sm;
    float* in_base = sm + IN_OFF;
    float* pw_s    = sm + PW_OFF;

    int tid = threadIdx.x;
    int co = tid & 63;
    int hl = tid >> 6;
    int rb = blockIdx.x, g = blockIdx.y, n = blockIdx.z;
    int h0 = rb * 4;

    const float* base = pred + (size_t)(n * CIN + g * CPG) * HWSZ;

    for (int i = tid; i < CPG * CPG; i += 256) {
        int cm = i >> 6, c = i & 63;
        pw_s[i] = g_pwkn[(size_t)n * ODK + (g * CPG + c) * CPG + cm];
    }

    int i0 = tid, i1 = tid + 256;
    int r0 = i0 / 66, c0p = i0 % 66;
    int r1 = i1 / 66, c1p = i1 % 66;
    bool v1 = (i1 < 396);
    int goff0 = refl(h0 + r0 - 1) * WW + refl(c0p - 1);
    int goff1 = v1 ? (refl(h0 + r1 - 1) * WW + refl(c1p - 1)) : 0;
    int s0 = r0 * 68 + c0p;
    int s1 = r1 * 68 + c1p;

    float q0 = base[goff0];
    float q1 = v1 ? base[goff1] : 0.f;
    // weight records: [n][ci][co][12], 48B-aligned, vector-loadable
    const float* wp = g_dwT + ((size_t)(n * CPG) * COUT + (g * CPG + co)) * WREC;

    ull acc2[32];
#pragma unroll
    for (int i = 0; i < 32; i++) acc2[i] = 0ULL;

    for (int ci = 0; ci < CPG; ci++) {
        float* ia = in_base + (ci & 1) * BUFSZ;
        float* ib = ia + 408;
        ia[s0] = q0;
        if (c0p) ib[s0 - 1] = q0;
        if (v1) {
            ia[s1] = q1;
            if (c1p) ib[s1 - 1] = q1;
        }
        // weight fetch for this ci (vectorized, L2-resident)
        const float* wr = wp + (size_t)ci * COUT * WREC;
        float4 wa = *(const float4*)(wr);
        float4 wb = *(const float4*)(wr + 4);
        float w8 = wr[8];
        __syncthreads();

        // input prefetch for ci+1 (overlaps compute)
        if (ci + 1 < CPG) {
            const float* pl = base + (size_t)(ci + 1) * HWSZ;
            q0 = pl[goff0];
            q1 = v1 ? pl[goff1] : 0.f;
        }

#pragma unroll
        for (int kh = 0; kh < 3; kh++) {
            const float* row  = &ia[(hl + kh) * 68];
            const float* rowB = row + 408;
            float d0 = (kh == 0) ? wa.x : (kh == 1) ? wa.w : wb.z;
            float d1 = (kh == 0) ? wa.y : (kh == 1) ? wb.x : wb.w;
            float d2 = (kh == 0) ? wa.z : (kh == 1) ? wb.y : w8;
            ull w0 = pk2(d0, d0);
            ull w1 = pk2(d1, d1);
            ull w2 = pk2(d2, d2);
#pragma unroll
            for (int c0 = 0; c0 < 64; c0 += 16) {
                const ull* ra = (const ull*)(row + c0);
                ulonglong2 a01 = *(const ulonglong2*)(ra);
                ulonglong2 a23 = *(const ulonglong2*)(ra + 2);
                ulonglong2 a45 = *(const ulonglong2*)(ra + 4);
                ulonglong2 a67 = *(const ulonglong2*)(ra + 6);
                ull a8 = ra[8];
                const ull* rbp = (const ull*)(rowB + c0);
                ulonglong2 b01 = *(const ulonglong2*)(rbp);
                ulonglong2 b23 = *(const ulonglong2*)(rbp + 2);
                ulonglong2 b45 = *(const ulonglong2*)(rbp + 4);
                ulonglong2 b67 = *(const ulonglong2*)(rbp + 6);
                int p = c0 >> 1;
                fma2(acc2[p + 0], w0, a01.x); fma2(acc2[p + 0], w1, b01.x); fma2(acc2[p + 0], w2, a01.y);
                fma2(acc2[p + 1], w0, a01.y); fma2(acc2[p + 1], w1, b01.y); fma2(acc2[p + 1], w2, a23.x);
                fma2(acc2[p + 2], w0, a23.x); fma2(acc2[p + 2], w1, b23.x); fma2(acc2[p + 2], w2, a23.y);
                fma2(acc2[p + 3], w0, a23.y); fma2(acc2[p + 3], w1, b23.y); fma2(acc2[p + 3], w2, a45.x);
                fma2(acc2[p + 4], w0, a45.x); fma2(acc2[p + 4], w1, b45.x); fma2(acc2[p + 4], w2, a45.y);
                fma2(acc2[p + 5], w0, a45.y); fma2(acc2[p + 5], w1, b45.y); fma2(acc2[p + 5], w2, a67.x);
                fma2(acc2[p + 6], w0, a67.x); fma2(acc2[p + 6], w1, b67.x); fma2(acc2[p + 6], w2, a67.y);
                fma2(acc2[p + 7], w0, a67.y); fma2(acc2[p + 7], w1, b67.y); fma2(acc2[p + 7], w2, a8);
            }
        }
    }

    __syncthreads();
    {
        ull* dst = (ull*)(depth_s + (co * 4 + hl) * 64);
#pragma unroll
        for (int i = 0; i < 32; i++) dst[i] = acc2[i];
    }
    __syncthreads();

#pragma unroll
    for (int i = 0; i < 32; i++) acc2[i] = 0ULL;
    for (int cm = 0; cm < CPG; cm++) {
        float v = pw_s[cm * 64 + co];
        ull vp = pk2(v, v);
        const ulonglong2* ds = (const ulonglong2*)(depth_s + (cm * 4 + hl) * 64);
#pragma unroll
        for (int i = 0; i < 16; i++) {
            ulonglong2 t = ds[i];
            fma2(acc2[2 * i],     vp, t.x);
            fma2(acc2[2 * i + 1], vp, t.y);
        }
    }

    float bias = g_pwbias[n * COUT + g * CPG + co];
    float* op = out + (((size_t)(n * COUT + g * CPG + co)) * HH + (h0 + hl)) * WW;
#pragma unroll
    for (int i = 0; i < 16; i++) {
        float x0, x1, x2, x3;
        upk2(acc2[2 * i], x0, x1);
        upk2(acc2[2 * i + 1], x2, x3);
        *(float4*)(op + 4 * i) = make_float4(x0 + bias, x1 + bias, x2 + bias, x3 + bias);
    }
}

// ---------------- Launch ----------------
extern "C" void kernel_launch(void* const* d_in, const int* in_sizes, int n_in,
                              void* d_out, int out_size) {
    const float* style = (const float*)d_in[0];
    const float* pred  = (const float*)d_in[1];
    const float* Wdk   = (const float*)d_in[2];
    const float* bdk   = (const float*)d_in[3];
    const float* Wpwk  = (const float*)d_in[4];
    const float* bpwk  = (const float*)d_in[5];
    const float* Wpwb  = (const float*)d_in[6];
    const float* bpwb  = (const float*)d_in[7];
    float* out = (float*)d_out;

    cudaFuncSetAttribute(k_conv, cudaFuncAttributeMaxDynamicSharedMemorySize, SMEM_CONV);

    k_pool<<<(NB * SD + 255) / 256, 256>>>(style);
    k_buildB<<<(NSTEP * NTIL * 32 + 255) / 256, 256>>>(style);
    k_pw<<<(ODK + COUT + 255) / 256, 256>>>(Wpwk, bpwk, Wpwb, bpwb);
    k_dk<<<(ODK / 128) * KSPLIT, 128>>>(Wdk);
    k_red<<<(DWSZ12 + 255) / 256, 256>>>(bdk);
    k_conv<<<dim3(HH / 4, NG, NB), 256, SMEM_CONV>>>(pred, out);
}

// round 17
// speedup vs baseline: 1.8967x; 1.5356x over previous
#include <cuda_runtime.h>
#include <cuda_bf16.h>
#include <cstdint>

// ---------------- Problem constants ----------------
#define NB    8
#define SD    512
#define CIN   512
#define COUT  512
#define CPG   64
#define NG    8
#define HH    64
#define WW    64
#define HWSZ  4096
#define KDK   4608
#define ODK   32768
#define NCOL  72
#define NSTEP 288          // KDK / 16
#define KSPLIT 4
#define QSTEP (NSTEP / KSPLIT)   // 72
#define NTIL  9            // 72 / 8
#define BSTG  (NTIL * 32)  // 288 uint4 per B stage
#define WREC  12           // padded taps per (n,ci,co) record
#define DWSZ12 (NB * CPG * COUT * WREC)

// conv-GEMM constants
#define S1    424          // input pair-plane stride (words), ≡8 mod 32 -> conflict-free
#define INW   (64 * S1)    // 27136 words: hi planes [0,32*424), lo at +13568
#define RING_F 3072        // 3 stages x 256 uint4 = 768 uint4 = 3072 words
#define PWOFF (INW + RING_F)         // 30208
#define SMEM_CONV ((PWOFF + CPG * CPG) * 4)   // 137216 B
#define AFRG_NG 9216       // 36*256 uint4 per (n,g)

typedef unsigned long long ull;

// ---------------- Device scratch ----------------
__device__ float g_pooled[NB * SD];
__device__ float g_pwkn[NB * ODK];
__device__ float g_pwbias[NB * COUT];
__device__ __align__(16) uint4 g_Bfrag[NSTEP * NTIL * 32];   // k_dk B fragments
__device__ __align__(16) float g_dwP[KSPLIT][DWSZ12];        // K-quarter partials [n][ci][co][12]
__device__ __align__(16) uint4 g_Afrag[64 * AFRG_NG];        // conv A fragments [ng][36][4mt][2][32]

// ---------------- f32x2 helpers ----------------
__device__ __forceinline__ ull pk2(float lo, float hi) {
    ull r;
    asm("mov.b64 %0, {%1, %2};" : "=l"(r) : "f"(lo), "f"(hi));
    return r;
}
__device__ __forceinline__ void upk2(ull v, float& lo, float& hi) {
    asm("mov.b64 {%0, %1}, %2;" : "=f"(lo), "=f"(hi) : "l"(v));
}
__device__ __forceinline__ void fma2(ull& d, ull a, ull b) {
    asm("fma.rn.f32x2 %0, %1, %2, %0;" : "+l"(d) : "l"(a), "l"(b));
}

// ---------------- mma.sync / cp.async helpers ----------------
__device__ __forceinline__ void mma16816(float* c, const uint32_t* a, uint32_t b0, uint32_t b1) {
    asm volatile(
        "mma.sync.aligned.m16n8k16.row.col.f32.bf16.bf16.f32 "
        "{%0,%1,%2,%3}, {%4,%5,%6,%7}, {%8,%9}, {%0,%1,%2,%3};"
        : "+f"(c[0]), "+f"(c[1]), "+f"(c[2]), "+f"(c[3])
        : "r"(a[0]), "r"(a[1]), "r"(a[2]), "r"(a[3]), "r"(b0), "r"(b1));
}
__device__ __forceinline__ uint32_t bf2u(__nv_bfloat162 h) {
    return *(const uint32_t*)&h;
}
__device__ __forceinline__ void cp16(uint32_t saddr, const void* gaddr) {
    asm volatile("cp.async.cg.shared.global [%0], [%1], 16;" :: "r"(saddr), "l"(gaddr));
}
#define CP_COMMIT() asm volatile("cp.async.commit_group;" ::: "memory")
#define CP_WAIT1()  asm volatile("cp.async.wait_group 1;" ::: "memory")

// ---------------- K0: 3x3 avg pool ----------------
__global__ void k_pool(const float* __restrict__ style) {
    int i = blockIdx.x * blockDim.x + threadIdx.x;
    if (i >= NB * SD) return;
    const float* p = style + (size_t)i * 25;
    float s = 0.f;
#pragma unroll
    for (int y = 0; y < 3; y++)
#pragma unroll
        for (int x = 0; x < 3; x++)
            s += p[y * 5 + x];
    g_pooled[i] = s * (1.0f / 9.0f);
}

// ---------------- K0b: build K-PERMUTED B fragments for k_dk ----------------
__device__ __forceinline__ float bval(const float* style, int n, int k) {
    int batch = n / 9, q = n % 9;
    int y = q / 3, x = q % 3;
    int sc = k / 9, rr = k % 9;
    int dy = rr / 3, dx = rr % 3;
    return style[((size_t)(batch * SD + sc) * 5 + (y + dy)) * 5 + (x + dx)];
}

__global__ void k_buildB(const float* __restrict__ style) {
    int i = blockIdx.x * blockDim.x + threadIdx.x;
    if (i >= NSTEP * NTIL * 32) return;
    int lane = i & 31;
    int t = i >> 5;
    int nt = t % NTIL;
    int s = t / NTIL;
    int n = nt * 8 + (lane >> 2);
    int kb = s * 16 + (lane & 3) * 4;
    float v[4];
#pragma unroll
    for (int q = 0; q < 4; q++) v[q] = bval(style, n, kb + q);
    __nv_bfloat16 h[4];
    float l[4];
#pragma unroll
    for (int q = 0; q < 4; q++) {
        h[q] = __float2bfloat16(v[q]);
        l[q] = v[q] - __bfloat162float(h[q]);
    }
    uint4 out;
    out.x = bf2u(__nv_bfloat162(h[0], h[1]));
    out.y = bf2u(__nv_bfloat162(h[2], h[3]));
    out.z = bf2u(__floats2bfloat162_rn(l[0], l[1]));
    out.w = bf2u(__floats2bfloat162_rn(l[2], l[3]));
    g_Bfrag[t * 32 + lane] = out;
}

// ---------------- K1: pooled GEMVs ----------------
__global__ void __launch_bounds__(256) k_pw(const float* __restrict__ Wpwk, const float* __restrict__ bpwk,
                                            const float* __restrict__ Wpwb, const float* __restrict__ bpwb) {
    __shared__ float ps[NB * SD];
    int tid = threadIdx.x;
    for (int i = tid; i < NB * SD; i += 256) ps[i] = g_pooled[i];
    __syncthreads();

    int r = blockIdx.x * 256 + tid;
    if (r >= ODK + COUT) return;
    bool isk = (r < ODK);
    int rr = isk ? r : (r - ODK);
    const float* w = isk ? (Wpwk + (size_t)r * SD) : (Wpwb + (size_t)rr * SD);
    float bias = isk ? bpwk[r] : bpwb[rr];

    float acc[NB];
#pragma unroll
    for (int n = 0; n < NB; n++) acc[n] = 0.f;

    for (int s = 0; s < SD; s += 4) {
        float4 wv = *(const float4*)(w + s);
#pragma unroll
        for (int n = 0; n < NB; n++) {
            const float* pp = &ps[n * SD + s];
            acc[n] += wv.x * pp[0] + wv.y * pp[1] + wv.z * pp[2] + wv.w * pp[3];
        }
    }
    if (isk) {
#pragma unroll
        for (int n = 0; n < NB; n++) g_pwkn[(size_t)n * ODK + r] = acc[n] + bias;
    } else {
#pragma unroll
        for (int n = 0; n < NB; n++) g_pwbias[n * COUT + rr] = acc[n] + bias;
    }
}

// ---------------- K2: dk GEMM (unchanged, writes g_dwP partials) ----------------
__global__ void __launch_bounds__(128) k_dk(const float* __restrict__ Wdk) {
    __shared__ __align__(16) uint4 Bs[3][BSTG];

    int tid = threadIdx.x;
    int wid = tid >> 5, lane = tid & 31;
    int bx = blockIdx.x;
    int kq = bx & 3;
    int mb = bx >> 2;
    int m0 = mb * 128 + wid * 32;
    int rA = m0 + (lane >> 2);
    int q4 = (lane & 3) * 4;
    int kc2 = (lane & 3) * 2;
    int sbase = kq * QSTEP;

    const float* aBase = Wdk + (size_t)rA * KDK + q4 + (size_t)sbase * 16;
    const size_t r8 = (size_t)8 * KDK;
    const uint4* bfrag0 = g_Bfrag + (size_t)sbase * BSTG;

    uint32_t bs_addr[3];
#pragma unroll
    for (int b = 0; b < 3; b++) bs_addr[b] = (uint32_t)__cvta_generic_to_shared(&Bs[b][0]);

    float acc[2][NTIL][4];
#pragma unroll
    for (int j = 0; j < 2; j++)
#pragma unroll
        for (int nt = 0; nt < NTIL; nt++)
#pragma unroll
            for (int q = 0; q < 4; q++) acc[j][nt][q] = 0.f;

    float4 pa[2][4];
#pragma unroll
    for (int d = 0; d < 2; d++) {
        const float* ap = aBase + (size_t)d * 16;
        pa[d][0] = *(const float4*)(ap);
        pa[d][1] = *(const float4*)(ap + r8);
        pa[d][2] = *(const float4*)(ap + 2 * r8);
        pa[d][3] = *(const float4*)(ap + 3 * r8);
    }
#pragma unroll
    for (int st = 0; st < 2; st++) {
        const uint4* src = bfrag0 + (size_t)st * BSTG;
        cp16(bs_addr[st] + tid * 16, src + tid);
        cp16(bs_addr[st] + (tid + 128) * 16, src + tid + 128);
        if (tid < 32) cp16(bs_addr[st] + (tid + 256) * 16, src + tid + 256);
        CP_COMMIT();
    }
    CP_WAIT1();
    __syncthreads();

    for (int s = 0; s < QSTEP; s++) {
        int cb = s & 1;
        uint32_t ahi[2][4], alo[2][4];
#pragma unroll
        for (int j = 0; j < 2; j++) {
            float4 fr = pa[cb][2 * j];
            float4 f8 = pa[cb][2 * j + 1];
            __nv_bfloat162 h0 = __floats2bfloat162_rn(fr.x, fr.y);
            __nv_bfloat162 h1 = __floats2bfloat162_rn(f8.x, f8.y);
            __nv_bfloat162 h2 = __floats2bfloat162_rn(fr.z, fr.w);
            __nv_bfloat162 h3 = __floats2bfloat162_rn(f8.z, f8.w);
            ahi[j][0] = bf2u(h0); ahi[j][1] = bf2u(h1); ahi[j][2] = bf2u(h2); ahi[j][3] = bf2u(h3);
            alo[j][0] = bf2u(__floats2bfloat162_rn(fr.x - __low2float(h0), fr.y - __high2float(h0)));
            alo[j][1] = bf2u(__floats2bfloat162_rn(f8.x - __low2float(h1), f8.y - __high2float(h1)));
            alo[j][2] = bf2u(__floats2bfloat162_rn(fr.z - __low2float(h2), fr.w - __high2float(h2)));
            alo[j][3] = bf2u(__floats2bfloat162_rn(f8.z - __low2float(h3), f8.w - __high2float(h3)));
        }
        if (s + 2 < QSTEP) {
            const float* ap = aBase + (size_t)(s + 2) * 16;
            pa[cb][0] = *(const float4*)(ap);
            pa[cb][1] = *(const float4*)(ap + r8);
            pa[cb][2] = *(const float4*)(ap + 2 * r8);
            pa[cb][3] = *(const float4*)(ap + 3 * r8);
        }
        if (s + 2 < QSTEP) {
            int nb = (s + 2) % 3;
            const uint4* src = bfrag0 + (size_t)(s + 2) * BSTG;
            cp16(bs_addr[nb] + tid * 16, src + tid);
            cp16(bs_addr[nb] + (tid + 128) * 16, src + tid + 128);
            if (tid < 32) cp16(bs_addr[nb] + (tid + 256) * 16, src + tid + 256);
        }
        CP_COMMIT();
        const uint4* bsrow = &Bs[s % 3][lane];
#pragma unroll
        for (int nt = 0; nt < NTIL; nt++) {
            uint4 b = bsrow[nt * 32];
            mma16816(acc[0][nt], ahi[0], b.x, b.y);
            mma16816(acc[0][nt], ahi[0], b.z, b.w);
            mma16816(acc[0][nt], alo[0], b.x, b.y);
            mma16816(acc[1][nt], ahi[1], b.x, b.y);
            mma16816(acc[1][nt], ahi[1], b.z, b.w);
            mma16816(acc[1][nt], alo[1], b.x, b.y);
        }
        CP_WAIT1();
        __syncthreads();
    }

    float* dst = g_dwP[kq];
#pragma unroll
    for (int j = 0; j < 2; j++) {
        int o0 = rA + 16 * j, o1 = o0 + 8;
        int co0 = o0 >> 6, ci0 = o0 & 63;
        int co1 = o1 >> 6, ci1 = o1 & 63;
#pragma unroll
        for (int nt = 0; nt < NTIL; nt++) {
            int colb = nt * 8 + kc2;
#pragma unroll
            for (int d = 0; d < 2; d++) {
                int col = colb + d;
                int n = col / 9, jj = col % 9;
                dst[((size_t)((n * CPG + ci0) * COUT) + co0) * WREC + jj] = acc[j][nt][d];
                dst[((size_t)((n * CPG + ci1) * COUT) + co1) * WREC + jj] = acc[j][nt][2 + d];
            }
        }
    }
}

// ---------------- K2b: build conv A fragments (replaces k_red) ----------------
// A frag for (ng, s=t*4+cq, mt, lane): rows co = mt*16 + lane>>2 (+8),
// k-slots identity: ci_local = cq*16 + 2*(lane&3) + {0,1,8,9}. value = sum partials + bias.
__global__ void __launch_bounds__(256) k_Afrag(const float* __restrict__ bdk) {
    int i = blockIdx.x * 256 + threadIdx.x;
    if (i >= 64 * 36 * 128) return;
    int lane = i & 31;
    int mt = (i >> 5) & 3;
    int s = (i >> 7) % 36;
    int ng = i / 4608;
    int n = ng >> 3, g = ng & 7;
    int t = s >> 2, cq = s & 3;
    int rowA = mt * 16 + (lane >> 2);
    int ci0 = cq * 16 + 2 * (lane & 3);

    float vA[4], vB[4];
#pragma unroll
    for (int q = 0; q < 4; q++) {
        int ci = ci0 + (q >> 1) * 8 + (q & 1);
        int coA = g * 64 + rowA;
        int coB = coA + 8;
        size_t ia = ((size_t)((n * CPG + ci) * COUT) + coA) * WREC + t;
        size_t ib = ((size_t)((n * CPG + ci) * COUT) + coB) * WREC + t;
        vA[q] = g_dwP[0][ia] + g_dwP[1][ia] + g_dwP[2][ia] + g_dwP[3][ia] + bdk[coA * 64 + ci];
        vB[q] = g_dwP[0][ib] + g_dwP[1][ib] + g_dwP[2][ib] + g_dwP[3][ib] + bdk[coB * 64 + ci];
    }
    __nv_bfloat162 h0 = __floats2bfloat162_rn(vA[0], vA[1]);
    __nv_bfloat162 h1 = __floats2bfloat162_rn(vB[0], vB[1]);
    __nv_bfloat162 h2 = __floats2bfloat162_rn(vA[2], vA[3]);
    __nv_bfloat162 h3 = __floats2bfloat162_rn(vB[2], vB[3]);
    uint4 hi, lo;
    hi.x = bf2u(h0); hi.y = bf2u(h1); hi.z = bf2u(h2); hi.w = bf2u(h3);
    lo.x = bf2u(__floats2bfloat162_rn(vA[0] - __low2float(h0), vA[1] - __high2float(h0)));
    lo.y = bf2u(__floats2bfloat162_rn(vB[0] - __low2float(h1), vB[1] - __high2float(h1)));
    lo.z = bf2u(__floats2bfloat162_rn(vA[2] - __low2float(h2), vA[3] - __high2float(h2)));
    lo.w = bf2u(__floats2bfloat162_rn(vB[2] - __low2float(h3), vB[3] - __high2float(h3)));
    size_t o = ((size_t)ng * 36 + s) * 256 + (mt * 2) * 32 + lane;
    g_Afrag[o] = hi;
    g_Afrag[o + 32] = lo;
}

// ---------------- K3: grouped conv via HMMA + f32x2 pointwise ----------------
__device__ __forceinline__ int refl(int i) {
    return i < 0 ? -i : (i > 63 ? 126 - i : i);
}

__global__ void __launch_bounds__(256) k_conv(const float* __restrict__ pred, float* __restrict__ out) {
    extern __shared__ __align__(16) float sm[];
    uint32_t* inw = (uint32_t*)sm;           // pair planes: hi [0,13568), lo [13568,27136)
    float* depth_s = sm;                     // alias after depthwise done (16384 floats)
    float* pw_s = sm + PWOFF;

    int tid = threadIdx.x;
    int lane = tid & 31, wid = tid >> 5;
    int rb = blockIdx.x, g = blockIdx.y, n = blockIdx.z;
    int h0 = rb * 4;
    int ng = n * 8 + g;

    const float* base = pred + (size_t)(n * CIN + g * CPG) * HWSZ;
    const uint4* afr = g_Afrag + (size_t)ng * AFRG_NG;
    uint32_t ringS = (uint32_t)__cvta_generic_to_shared(sm + INW);

    // A-ring prologue: stages 0,1
    cp16(ringS + tid * 16, afr + tid);
    CP_COMMIT();
    cp16(ringS + 4096 + tid * 16, afr + 256 + tid);
    CP_COMMIT();

    // pw weights preload
    for (int i = tid; i < CPG * CPG; i += 256) {
        int cm = i >> 6, c = i & 63;
        pw_s[i] = g_pwkn[(size_t)n * ODK + (g * CPG + c) * CPG + cm];
    }

    // input load: 32 ci-pairs, halo 6x66 (stride 68), bf16 hi/lo pair-packed
    {
        int i0 = tid, i1 = tid + 256;
        int r0 = i0 / 66, c0p = i0 % 66;
        int r1 = i1 / 66, c1p = i1 % 66;
        bool v1 = (i1 < 396);
        int go0 = refl(h0 + r0 - 1) * WW + refl(c0p - 1);
        int go1 = v1 ? (refl(h0 + r1 - 1) * WW + refl(c1p - 1)) : 0;
        int hw0 = r0 * 68 + c0p;
        int hw1 = r1 * 68 + c1p;
#pragma unroll 4
        for (int pr = 0; pr < 32; pr++) {
            const float* p0 = base + (size_t)(2 * pr) * HWSZ;
            const float* p1 = p0 + HWSZ;
            float x0 = p0[go0], y0 = p1[go0];
            float x1 = v1 ? p0[go1] : 0.f;
            float y1 = v1 ? p1[go1] : 0.f;
            __nv_bfloat162 h = __floats2bfloat162_rn(x0, y0);
            inw[pr * S1 + hw0] = bf2u(h);
            inw[13568 + pr * S1 + hw0] =
                bf2u(__floats2bfloat162_rn(x0 - __low2float(h), y0 - __high2float(h)));
            if (v1) {
                __nv_bfloat162 h2 = __floats2bfloat162_rn(x1, y1);
                inw[pr * S1 + hw1] = bf2u(h2);
                inw[13568 + pr * S1 + hw1] =
                    bf2u(__floats2bfloat162_rn(x1 - __low2float(h2), y1 - __high2float(h2)));
            }
        }
    }

    // per-lane n-tile geometry: warp owns n-tiles wid*4..+3; n-col = lane>>2
    int hwb[4];
#pragma unroll
    for (int j = 0; j < 4; j++) {
        int p = (wid * 4 + j) * 8 + (lane >> 2);
        hwb[j] = (p >> 6) * 68 + (p & 63);
    }

    float acc[4][4][4];
#pragma unroll
    for (int j = 0; j < 4; j++)
#pragma unroll
        for (int mt = 0; mt < 4; mt++)
#pragma unroll
            for (int q = 0; q < 4; q++) acc[j][mt][q] = 0.f;

    const uint4* ring = (const uint4*)(sm + INW);
    int srot = 0;
    for (int t = 0; t < 9; t++) {
        int dy = t / 3, dx = t - dy * 3;
        int hoff = dy * 68 + dx;
#pragma unroll
        for (int cq = 0; cq < 4; cq++) {
            int s = t * 4 + cq;
            CP_WAIT1();
            __syncthreads();   // ring stage s ready+visible; also covers input STS at s=0
            const uint4* rg = ring + srot * 256;
            uint4 ah[4], al[4];
#pragma unroll
            for (int mt = 0; mt < 4; mt++) {
                ah[mt] = rg[mt * 64 + lane];
                al[mt] = rg[mt * 64 + 32 + lane];
            }
            if (s + 2 < 36) {
                int nxt = srot + 2;
                if (nxt >= 3) nxt -= 3;
                cp16(ringS + nxt * 4096 + tid * 16, afr + (s + 2) * 256 + tid);
            }
            CP_COMMIT();
            int pb = cq * 8 + (lane & 3);
#pragma unroll
            for (int j = 0; j < 4; j++) {
                int hw = hwb[j] + hoff;
                uint32_t b0h = inw[pb * S1 + hw];
                uint32_t b1h = inw[(pb + 4) * S1 + hw];
                uint32_t b0l = inw[13568 + pb * S1 + hw];
                uint32_t b1l = inw[13568 + (pb + 4) * S1 + hw];
#pragma unroll
                for (int mt = 0; mt < 4; mt++) {
                    mma16816(acc[j][mt], (const uint32_t*)&ah[mt], b0h, b1h);
                    mma16816(acc[j][mt], (const uint32_t*)&ah[mt], b0l, b1l);
                    mma16816(acc[j][mt], (const uint32_t*)&al[mt], b0h, b1h);
                }
            }
            srot = (srot == 2) ? 0 : srot + 1;
        }
    }

    __syncthreads();   // all MMAs done reading input smem
    // store depth fp32 into depth_s[co][256] (aliases input region)
#pragma unroll
    for (int j = 0; j < 4; j++) {
        int p = (wid * 4 + j) * 8 + 2 * (lane & 3);
#pragma unroll
        for (int mt = 0; mt < 4; mt++) {
            int co = mt * 16 + (lane >> 2);
            *(float2*)&depth_s[co * 256 + p] = make_float2(acc[j][mt][0], acc[j][mt][1]);
            *(float2*)&depth_s[(co + 8) * 256 + p] = make_float2(acc[j][mt][2], acc[j][mt][3]);
        }
    }
    __syncthreads();

    // pointwise (f32x2, proven): thread = (co', hl)
    int co = tid & 63;
    int hl = tid >> 6;
    ull po[32];
#pragma unroll
    for (int i = 0; i < 32; i++) po[i] = 0ULL;
    for (int cm = 0; cm < CPG; cm++) {
        float v = pw_s[cm * 64 + co];
        ull vp = pk2(v, v);
        const ulonglong2* ds = (const ulonglong2*)(depth_s + cm * 256 + hl * 64);
#pragma unroll
        for (int i = 0; i < 16; i++) {
            ulonglong2 tt = ds[i];
            fma2(po[2 * i], vp, tt.x);
            fma2(po[2 * i + 1], vp, tt.y);
        }
    }

    float bias = g_pwbias[n * COUT + g * CPG + co];
    float* op = out + (((size_t)(n * COUT + g * CPG + co)) * HH + (h0 + hl)) * WW;
#pragma unroll
    for (int i = 0; i < 16; i++) {
        float x0, x1, x2, x3;
        upk2(po[2 * i], x0, x1);
        upk2(po[2 * i + 1], x2, x3);
        *(float4*)(op + 4 * i) = make_float4(x0 + bias, x1 + bias, x2 + bias, x3 + bias);
    }
}

// ---------------- Launch ----------------
extern "C" void kernel_launch(void* const* d_in, const int* in_sizes, int n_in,
                              void* d_out, int out_size) {
    const float* style = (const float*)d_in[0];
    const float* pred  = (const float*)d_in[1];
    const float* Wdk   = (const float*)d_in[2];
    const float* bdk   = (const float*)d_in[3];
    const float* Wpwk  = (const float*)d_in[4];
    const float* bpwk  = (const float*)d_in[5];
    const float* Wpwb  = (const float*)d_in[6];
    const float* bpwb  = (const float*)d_in[7];
    float* out = (float*)d_out;

    cudaFuncSetAttribute(k_conv, cudaFuncAttributeMaxDynamicSharedMemorySize, SMEM_CONV);

    k_pool<<<(NB * SD + 255) / 256, 256>>>(style);
    k_buildB<<<(NSTEP * NTIL * 32 + 255) / 256, 256>>>(style);
    k_pw<<<(ODK + COUT + 255) / 256, 256>>>(Wpwk, bpwk, Wpwb, bpwb);
    k_dk<<<(ODK / 128) * KSPLIT, 128>>>(Wdk);
    k_Afrag<<<(64 * 36 * 128 + 255) / 256, 256>>>(bdk);
    k_conv<<<dim3(HH / 4, NG, NB), 256, SMEM_CONV>>>(pred, out);
}